// round 14
// baseline (speedup 1.0000x reference)
#include <cuda_runtime.h>
#include <math.h>

#define D   256
#define NQ  512
#define NK  512

typedef unsigned long long ull;

// ---------------- scratch ----------------
__device__ __align__(16) float g_aq[D * NQ];      // (d, n)  full f32
__device__ __align__(16) float g_ak[D * NK];      // (d, m)  full f32
__device__ __align__(16) float g_probT[NK * NQ];  // (m, n)  tf32-rounded
__device__ __align__(16) float g_msg[D * NQ];     // (d, n)  tf32-rounded
__device__ __align__(16) float g_h2[2 * D * NQ];  // (o, n)  tf32-rounded

// tf32-rounded input copies
__device__ __align__(16) float g_w1t[D * 2 * D];
__device__ __align__(16) float g_xt [D * NQ];
__device__ __align__(16) float g_srct[D * NK];
__device__ __align__(16) float g_wat[2 * D * 2 * D];
__device__ __align__(16) float g_wbt[D * 2 * D];

// ---------------- helpers ----------------
__device__ __forceinline__ float f2tf(float f) {
    unsigned u; asm("cvt.rna.tf32.f32 %0, %1;" : "=r"(u) : "f"(f));
    return __uint_as_float(u);
}
__device__ __forceinline__ void mma_tf32(float4& c,
    float a0, float a1, float a2, float a3, float b0, float b1)
{
    asm("mma.sync.aligned.m16n8k8.row.col.f32.tf32.tf32.f32 "
        "{%0,%1,%2,%3}, {%4,%5,%6,%7}, {%8,%9}, {%0,%1,%2,%3};"
        : "+f"(c.x), "+f"(c.y), "+f"(c.z), "+f"(c.w)
        : "r"(__float_as_uint(a0)), "r"(__float_as_uint(a1)),
          "r"(__float_as_uint(a2)), "r"(__float_as_uint(a3)),
          "r"(__float_as_uint(b0)), "r"(__float_as_uint(b1)));
}
__device__ __forceinline__ unsigned s2u(const void* p) {
    return (unsigned)__cvta_generic_to_shared(p);
}
__device__ __forceinline__ void cp16(unsigned dst, const void* src) {
    asm volatile("cp.async.ca.shared.global [%0], [%1], 16;" :: "r"(dst), "l"(src));
}
#define CP_COMMIT() asm volatile("cp.async.commit_group;")
#define CP_WAIT2()  asm volatile("cp.async.wait_group 2;")

// packed f32x2 helpers
__device__ __forceinline__ ull pack2(float lo, float hi) {
    ull r; asm("mov.b64 %0,{%1,%2};" : "=l"(r) : "f"(lo), "f"(hi)); return r;
}
__device__ __forceinline__ float2 unpack2(ull v) {
    float2 r; asm("mov.b64 {%0,%1},%2;" : "=f"(r.x), "=f"(r.y) : "l"(v)); return r;
}
__device__ __forceinline__ ull fma2(ull a, ull b, ull c) {
    ull d; asm("fma.rn.f32x2 %0,%1,%2,%3;" : "=l"(d) : "l"(a), "l"(b), "l"(c)); return d;
}
__device__ __forceinline__ ull add2(ull a, ull b) {
    ull d; asm("add.rn.f32x2 %0,%1,%2;" : "=l"(d) : "l"(a), "l"(b)); return d;
}

// ---------------- pre-convert inputs to tf32 (2 float4 / thread) ----------
__global__ void __launch_bounds__(256) k_cvt(
    const float* __restrict__ x, const float* __restrict__ src,
    const float* __restrict__ w1, const float* __restrict__ wa,
    const float* __restrict__ wb)
{
    const int b = blockIdx.x;
    const float* s; float* d; int off;
    if      (b < 64)  { s = w1;  d = g_w1t;  off = b; }
    else if (b < 128) { s = x;   d = g_xt;   off = b - 64; }
    else if (b < 192) { s = src; d = g_srct; off = b - 128; }
    else if (b < 320) { s = wa;  d = g_wat;  off = b - 192; }
    else              { s = wb;  d = g_wbt;  off = b - 320; }
    const int i = off * 512 + threadIdx.x * 2;
    #pragma unroll
    for (int p = 0; p < 2; p++) {
        float4 v = ((const float4*)s)[i + p];
        v.x = f2tf(v.x); v.y = f2tf(v.y); v.z = f2tf(v.z); v.w = f2tf(v.w);
        ((float4*)d)[i + p] = v;
    }
}

// ---------- Core A: TF32 MMA, tile 32 x 64, 256 thr, 3-stage cp.async ------
template<bool DUAL, bool ROUND>
__device__ __forceinline__ void gemmA(
    const float* __restrict__ W, const float* __restrict__ X0,
    const float* __restrict__ X1, const float* __restrict__ bias,
    float* __restrict__ out, int K, bool relu)
{
    const int n0   = blockIdx.x * 64;
    const int o0   = blockIdx.y * 32;
    const int tid  = threadIdx.x;
    const int warp = tid >> 5, lane = tid & 31;
    const int g    = lane >> 2, t4 = lane & 3;
    const int mt   = warp & 1;
    const int ng   = (warp >> 1) * 16;

    __shared__ __align__(16) float sW[3][32 * 36];
    __shared__ __align__(16) float sX[3][32 * 72];

    const int wo = tid >> 3, wf = tid & 7;
    const int xn4 = tid & 15, xk = tid >> 4;

    const int NIT = K >> 5;

    float4 acc[2] = {make_float4(0.f,0.f,0.f,0.f), make_float4(0.f,0.f,0.f,0.f)};

    auto issue = [&](int tile, int st) {
        const int k0 = tile * 32;
        cp16(s2u(&sW[st][wo * 36 + wf * 4]), &W[(o0 + wo) * 512 + k0 + wf * 4]);
        #pragma unroll
        for (int p = 0; p < 2; p++) {
            const int c = k0 + xk + p * 16;
            const float* src = (!DUAL || c < 256)
                ? &X0[c * 512 + n0 + xn4 * 4]
                : &X1[(c - 256) * 512 + n0 + xn4 * 4];
            cp16(s2u(&sX[st][(xk + p * 16) * 72 + xn4 * 4]), src);
        }
    };

    issue(0, 0); CP_COMMIT();
    issue(1, 1); CP_COMMIT();

    for (int it = 0; it < NIT; it++) {
        const int st = it % 3;
        if (it + 2 < NIT) issue(it + 2, (it + 2) % 3);
        CP_COMMIT();
        CP_WAIT2();
        __syncthreads();
        const int ob = mt * 16 + g;
        #pragma unroll
        for (int s = 0; s < 4; s++) {
            const int ks = s * 8;
            float a0 = sW[st][(ob    ) * 36 + ks + t4];
            float a1 = sW[st][(ob + 8) * 36 + ks + t4];
            float a2 = sW[st][(ob    ) * 36 + ks + t4 + 4];
            float a3 = sW[st][(ob + 8) * 36 + ks + t4 + 4];
            #pragma unroll
            for (int j = 0; j < 2; j++) {
                const int nc = ng + j * 8 + g;
                float b0 = sX[st][(ks + t4    ) * 72 + nc];
                float b1 = sX[st][(ks + t4 + 4) * 72 + nc];
                mma_tf32(acc[j], a0, a1, a2, a3, b0, b1);
            }
        }
        __syncthreads();
    }

    const int oA = o0 + mt * 16 + g;
    const int oB = oA + 8;
    const float bA = bias ? bias[oA] : 0.f;
    const float bB = bias ? bias[oB] : 0.f;
    #pragma unroll
    for (int j = 0; j < 2; j++) {
        float c0 = acc[j].x + bA, c1 = acc[j].y + bA;
        float c2 = acc[j].z + bB, c3 = acc[j].w + bB;
        if (relu) {
            c0 = fmaxf(c0, 0.f); c1 = fmaxf(c1, 0.f);
            c2 = fmaxf(c2, 0.f); c3 = fmaxf(c3, 0.f);
        }
        if (ROUND) { c0 = f2tf(c0); c1 = f2tf(c1); c2 = f2tf(c2); c3 = f2tf(c3); }
        const int nc = n0 + ng + j * 8 + 2 * t4;
        *(float2*)&out[oA * 512 + nc] = make_float2(c0, c1);
        *(float2*)&out[oB * 512 + nc] = make_float2(c2, c3);
    }
}

// ---------- Core B: TF32 MMA, tile 16 x 64, 256 thr, split-k-in-tile -------
// 8 warps = 2 k-halves (kw) x 4 n-groups of 16 (wq). Each warp: 2 mma per
// a-fragment load. Partials reduced through smem.
template<bool ROUND>
__device__ __forceinline__ void gemmB(
    const float* __restrict__ W, const float* __restrict__ X0,
    const float* __restrict__ bias, float* __restrict__ out, int K)
{
    const int n0   = blockIdx.x * 64;
    const int o0   = blockIdx.y * 16;
    const int tid  = threadIdx.x;
    const int warp = tid >> 5, lane = tid & 31;
    const int g    = lane >> 2, t4 = lane & 3;
    const int kw   = warp >> 2;        // k half of tile
    const int wq   = warp & 3;         // n group (16 wide)

    __shared__ __align__(16) float sW[3][16 * 36];
    __shared__ __align__(16) float sX[3][32 * 72];
    __shared__ __align__(16) float4 sRb[4][32][2];

    const int wo = tid >> 3, wf = tid & 7;          // W: tid<128 only
    const int xn4 = tid & 15, xk = tid >> 4;

    const int NIT = K >> 5;

    float4 acc[2] = {make_float4(0.f,0.f,0.f,0.f), make_float4(0.f,0.f,0.f,0.f)};

    auto issue = [&](int tile, int st) {
        const int k0 = tile * 32;
        if (tid < 128)
            cp16(s2u(&sW[st][wo * 36 + wf * 4]), &W[(o0 + wo) * 512 + k0 + wf * 4]);
        #pragma unroll
        for (int p = 0; p < 2; p++) {
            const int c = k0 + xk + p * 16;
            cp16(s2u(&sX[st][(xk + p * 16) * 72 + xn4 * 4]),
                 &X0[c * 512 + n0 + xn4 * 4]);
        }
    };

    issue(0, 0); CP_COMMIT();
    issue(1, 1); CP_COMMIT();

    for (int it = 0; it < NIT; it++) {
        const int st = it % 3;
        if (it + 2 < NIT) issue(it + 2, (it + 2) % 3);
        CP_COMMIT();
        CP_WAIT2();
        __syncthreads();
        #pragma unroll
        for (int ss = 0; ss < 2; ss++) {
            const int ks = (kw * 2 + ss) * 8;
            float a0 = sW[st][(g    ) * 36 + ks + t4];
            float a1 = sW[st][(g + 8) * 36 + ks + t4];
            float a2 = sW[st][(g    ) * 36 + ks + t4 + 4];
            float a3 = sW[st][(g + 8) * 36 + ks + t4 + 4];
            #pragma unroll
            for (int j = 0; j < 2; j++) {
                const int nc = wq * 16 + j * 8 + g;
                float b0 = sX[st][(ks + t4    ) * 72 + nc];
                float b1 = sX[st][(ks + t4 + 4) * 72 + nc];
                mma_tf32(acc[j], a0, a1, a2, a3, b0, b1);
            }
        }
        __syncthreads();
    }

    if (kw == 1) {
        sRb[wq][lane][0] = acc[0];
        sRb[wq][lane][1] = acc[1];
    }
    __syncthreads();
    if (kw == 0) {
        const int oA = o0 + g, oB = oA + 8;
        const float bA = bias ? bias[oA] : 0.f;
        const float bB = bias ? bias[oB] : 0.f;
        #pragma unroll
        for (int j = 0; j < 2; j++) {
            float4 r = sRb[wq][lane][j];
            float c0 = acc[j].x + r.x + bA;
            float c1 = acc[j].y + r.y + bA;
            float c2 = acc[j].z + r.z + bB;
            float c3 = acc[j].w + r.w + bB;
            if (ROUND) { c0 = f2tf(c0); c1 = f2tf(c1); c2 = f2tf(c2); c3 = f2tf(c3); }
            const int nc = n0 + wq * 16 + j * 8 + 2 * t4;
            *(float2*)&out[oA * 512 + nc] = make_float2(c0, c1);
            *(float2*)&out[oB * 512 + nc] = make_float2(c2, c3);
        }
    }
}

// ---------------- stage kernels ----------------

__global__ void __launch_bounds__(256) k_qk(const float* __restrict__ b1)
{
    if (blockIdx.z == 0)
        gemmA<false, false>(g_w1t,       g_xt,   nullptr, b1,      g_aq, 256, false);
    else
        gemmA<false, false>(g_w1t + 256, g_srct, nullptr, nullptr, g_ak, 256, false);
}

// scores[n][m] = sum_d w2[d]*relu(aq+ak) + b2, via (0.5w)*(s+|s|), packed f32x2
__global__ void __launch_bounds__(256) k_score(
    const float* __restrict__ w2, const float* __restrict__ b2,
    float* __restrict__ scores)
{
    const int m0  = blockIdx.x * 64;
    const int n0  = blockIdx.y * 32;
    const int tid = threadIdx.x;
    const int wg  = tid >> 7;
    const int t   = tid & 127;
    const int mI  = t & 15;
    const int nG  = t >> 4;

    __shared__ __align__(16) float sA[2][32 * 36];
    __shared__ __align__(16) float sB[2][32 * 68];
    __shared__ ull swp[2][32];
    __shared__ __align__(16) float sR[128 * 16];

    const int an4 = t & 7,  adr = t >> 3;
    const int bm4 = t & 15, bdr = t >> 4;
    const int db  = wg * 128;
    const ull MASK = 0x7fffffff7fffffffULL;

    float4 ra[2], rb[4];
    float rwv;
    ull acc[4][2] = {};

    #pragma unroll
    for (int p = 0; p < 2; p++)
        ra[p] = *(const float4*)&g_aq[(db + adr + p * 16) * 512 + n0 + an4 * 4];
    #pragma unroll
    for (int p = 0; p < 4; p++)
        rb[p] = *(const float4*)&g_ak[(db + bdr + p * 8) * 512 + m0 + bm4 * 4];
    rwv = (t < 32) ? w2[db + t] : 0.f;

    for (int it = 0; it < 4; it++) {
        __syncthreads();
        #pragma unroll
        for (int p = 0; p < 2; p++)
            *(float4*)&sA[wg][(adr + p * 16) * 36 + an4 * 4] = ra[p];
        #pragma unroll
        for (int p = 0; p < 4; p++)
            *(float4*)&sB[wg][(bdr + p * 8) * 68 + bm4 * 4] = rb[p];
        if (t < 32) { const float hw = 0.5f * rwv; swp[wg][t] = pack2(hw, hw); }
        __syncthreads();

        if (it + 1 < 4) {
            const int d0 = db + (it + 1) * 32;
            #pragma unroll
            for (int p = 0; p < 2; p++)
                ra[p] = *(const float4*)&g_aq[(d0 + adr + p * 16) * 512 + n0 + an4 * 4];
            #pragma unroll
            for (int p = 0; p < 4; p++)
                rb[p] = *(const float4*)&g_ak[(d0 + bdr + p * 8) * 512 + m0 + bm4 * 4];
            if (t < 32) rwv = w2[d0 + t];
        }

        #pragma unroll 8
        for (int d = 0; d < 32; d++) {
            float4 av = *(const float4*)&sA[wg][d * 36 + nG * 4];
            ulonglong2 bb = *(const ulonglong2*)&sB[wg][d * 68 + mI * 4];
            ull wd = swp[wg][d];
            float a[4] = {av.x, av.y, av.z, av.w};
            #pragma unroll
            for (int j = 0; j < 4; j++) {
                ull aj = pack2(a[j], a[j]);
                ull s0 = add2(aj, bb.x);
                acc[j][0] = fma2(wd, add2(s0, s0 & MASK), acc[j][0]);
                ull s1 = add2(aj, bb.y);
                acc[j][1] = fma2(wd, add2(s1, s1 & MASK), acc[j][1]);
            }
        }
    }

    float4 f[4];
    #pragma unroll
    for (int j = 0; j < 4; j++) {
        float2 lo = unpack2(acc[j][0]), hi = unpack2(acc[j][1]);
        f[j] = make_float4(lo.x, lo.y, hi.x, hi.y);
    }
    if (wg == 1) {
        #pragma unroll
        for (int j = 0; j < 4; j++)
            *(float4*)&sR[(t * 4 + j) * 4] = f[j];
    }
    __syncthreads();
    if (wg == 0) {
        const float bs = b2[0];
        #pragma unroll
        for (int j = 0; j < 4; j++) {
            float4 r = *(const float4*)&sR[(t * 4 + j) * 4];
            const int n = n0 + nG * 4 + j;
            float4 v = f[j];
            v.x += r.x + bs; v.y += r.y + bs;
            v.z += r.z + bs; v.w += r.w + bs;
            *(float4*)&scores[n * 512 + m0 + mI * 4] = v;
        }
    }
}

// softmax -> transposed prob (tf32). 128 blocks x 512 thr; 4 warps per row.
__global__ void __launch_bounds__(512) k_softmaxT(const float* __restrict__ scores)
{
    const int n0   = blockIdx.x * 4;
    const int tid  = threadIdx.x;
    const int w    = tid >> 5, lane = tid & 31;
    const int r    = w >> 2, h = w & 3;          // row, quarter
    __shared__ float sP[4][516];
    __shared__ float sM[4][4], sS[4][4];

    const float* row = scores + (n0 + r) * 512 + h * 128;
    float v[4];
    float mx = -1e30f;
    #pragma unroll
    for (int i = 0; i < 4; i++) { v[i] = row[lane + 32 * i]; mx = fmaxf(mx, v[i]); }
    #pragma unroll
    for (int o = 16; o; o >>= 1) mx = fmaxf(mx, __shfl_xor_sync(0xffffffffu, mx, o));
    if (lane == 0) sM[r][h] = mx;
    __syncthreads();
    const float m = fmaxf(fmaxf(sM[r][0], sM[r][1]), fmaxf(sM[r][2], sM[r][3]));
    float s = 0.f;
    #pragma unroll
    for (int i = 0; i < 4; i++) { v[i] = __expf(v[i] - m); s += v[i]; }
    #pragma unroll
    for (int o = 16; o; o >>= 1) s += __shfl_xor_sync(0xffffffffu, s, o);
    if (lane == 0) sS[r][h] = s;
    __syncthreads();
    const float inv = 1.f / (sS[r][0] + sS[r][1] + sS[r][2] + sS[r][3]);
    #pragma unroll
    for (int i = 0; i < 4; i++)
        sP[r][h * 128 + lane + 32 * i] = v[i] * inv;
    __syncthreads();
    {
        const int mi = tid;   // 512 m values, one per thread
        float4 tv = make_float4(f2tf(sP[0][mi]), f2tf(sP[1][mi]),
                                f2tf(sP[2][mi]), f2tf(sP[3][mi]));
        *(float4*)&g_probT[mi * 512 + n0] = tv;
    }
}

// message = src @ probT          grid (8,16), 256 thr
__global__ void __launch_bounds__(256) k_msg()
{
    gemmB<true>(g_srct, g_probT, nullptr, g_msg, 512);
}

// h2 = relu(wa @ [x; msg] + ba)  grid (8,16), 256 thr
__global__ void __launch_bounds__(256) k_h2(const float* __restrict__ ba)
{
    gemmA<true, true>(g_wat, g_xt, g_msg, ba, g_h2, 512, true);
}

// y = wb @ h2 + bb               grid (8,16), 256 thr
__global__ void __launch_bounds__(256) k_y(
    const float* __restrict__ bb, float* __restrict__ y)
{
    gemmB<false>(g_wbt, g_h2, bb, y, 512);
}

// ---------------- launch ----------------
extern "C" void kernel_launch(void* const* d_in, const int* in_sizes, int n_in,
                              void* d_out, int out_size)
{
    const float* x   = (const float*)d_in[0];
    const float* src = (const float*)d_in[1];
    const float* w1  = (const float*)d_in[2];
    const float* b1  = (const float*)d_in[3];
    const float* w2  = (const float*)d_in[4];
    const float* b2  = (const float*)d_in[5];
    const float* wa  = (const float*)d_in[6];
    const float* ba  = (const float*)d_in[7];
    const float* wb  = (const float*)d_in[8];
    const float* bb  = (const float*)d_in[9];

    float* y      = (float*)d_out;   // (1, D, NQ)
    float* scores = y + D * NQ;      // (1, NQ, NK)

    k_cvt     <<<384,           256>>>(x, src, w1, wa, wb);
    k_qk      <<<dim3(8, 8, 2), 256>>>(b1);
    k_score   <<<dim3(8, 16),   256>>>(w2, b2, scores);
    k_softmaxT<<<128,           512>>>(scores);
    k_msg     <<<dim3(8, 16),   256>>>();
    k_h2      <<<dim3(8, 16),   256>>>(ba);
    k_y       <<<dim3(8, 16),   256>>>(bb, y);
}

// round 17
// speedup vs baseline: 1.0057x; 1.0057x over previous
#include <cuda_runtime.h>
#include <math.h>

#define D   256
#define NQ  512
#define NK  512

// ---------------- scratch ----------------
__device__ __align__(16) float g_aq[D * NQ];       // (d, n) f32
__device__ __align__(16) float g_ak[D * NK];       // (d, m) f32
__device__ __align__(16) float g_prob[NQ * NK];    // (n, m) tf32
__device__ __align__(16) float g_msgT[NQ * D];     // (n, d) tf32
__device__ __align__(16) float g_h2T[NQ * 2 * D];  // (n, o) tf32
__device__ __align__(16) float g_yT[NQ * D];       // (n, o) f32

// tf32 input copies (native + transposed layouts)
__device__ __align__(16) float g_w1t[D * 2 * D];     // (d, c)   256x512
__device__ __align__(16) float g_xt [D * NQ];        // (c, n)   256x512
__device__ __align__(16) float g_srct[D * NK];       // (c, m)   256x512
__device__ __align__(16) float g_xTt [NQ * D];       // (n, c)   512x256
__device__ __align__(16) float g_srcTt[NK * D];      // (m, c)   512x256
__device__ __align__(16) float g_waTt[2 * D * 2 * D];// (c, o)   512x512
__device__ __align__(16) float g_wbTt[2 * D * D];    // (c, o)   512x256

// ---------------- helpers ----------------
__device__ __forceinline__ float f2tf(float f) {
    unsigned u; asm("cvt.rna.tf32.f32 %0, %1;" : "=r"(u) : "f"(f));
    return __uint_as_float(u);
}
__device__ __forceinline__ void mma_tf32(float4& c,
    float a0, float a1, float a2, float a3, float b0, float b1)
{
    asm("mma.sync.aligned.m16n8k8.row.col.f32.tf32.tf32.f32 "
        "{%0,%1,%2,%3}, {%4,%5,%6,%7}, {%8,%9}, {%0,%1,%2,%3};"
        : "+f"(c.x), "+f"(c.y), "+f"(c.z), "+f"(c.w)
        : "r"(__float_as_uint(a0)), "r"(__float_as_uint(a1)),
          "r"(__float_as_uint(a2)), "r"(__float_as_uint(a3)),
          "r"(__float_as_uint(b0)), "r"(__float_as_uint(b1)));
}
__device__ __forceinline__ unsigned s2u(const void* p) {
    return (unsigned)__cvta_generic_to_shared(p);
}
__device__ __forceinline__ void cp16(unsigned dst, const void* src) {
    asm volatile("cp.async.ca.shared.global [%0], [%1], 16;" :: "r"(dst), "l"(src));
}
#define CP_COMMIT() asm volatile("cp.async.commit_group;")
#define CP_WAIT2()  asm volatile("cp.async.wait_group 2;")

// ---------------- pre-pass: tf32 copies + transposes ----------------
// blocks 0..95: native copies (w1, x, src) — 4 float4/thread (FULL coverage).
// blocks 96..735: 32x32 smem-tile transposes with tf32 rounding.
__global__ void __launch_bounds__(256) k_cvt(
    const float* __restrict__ x, const float* __restrict__ src,
    const float* __restrict__ w1, const float* __restrict__ wa,
    const float* __restrict__ wb)
{
    const int b   = blockIdx.x;
    const int tid = threadIdx.x;
    if (b < 96) {
        const float* s; float* d; int off;
        if      (b < 32) { s = w1;  d = g_w1t;  off = b; }
        else if (b < 64) { s = x;   d = g_xt;   off = b - 32; }
        else             { s = src; d = g_srct; off = b - 64; }
        // 256x512 floats = 32768 float4; 32 blocks -> 1024 float4/block
        #pragma unroll
        for (int p = 0; p < 4; p++) {
            const int i = off * 1024 + p * 256 + tid;
            float4 v = ((const float4*)s)[i];
            v.x = f2tf(v.x); v.y = f2tf(v.y); v.z = f2tf(v.z); v.w = f2tf(v.w);
            ((float4*)d)[i] = v;
        }
        return;
    }
    // transposes
    const float* in; float* out; int ldi, ldo, t;
    if      (b < 224) { in = x;   out = g_xTt;   ldi = 512; ldo = 256; t = b - 96; }
    else if (b < 352) { in = src; out = g_srcTt; ldi = 512; ldo = 256; t = b - 224; }
    else if (b < 608) { in = wa;  out = g_waTt;  ldi = 512; ldo = 512; t = b - 352; }
    else              { in = wb;  out = g_wbTt;  ldi = 512; ldo = 256; t = b - 608; }
    const int tj = t & 15, ti = t >> 4;
    const int i0 = ti * 32, j0 = tj * 32;

    __shared__ float s[32 * 33];
    const int r = tid >> 3, c4 = tid & 7;
    float4 v = *(const float4*)&in[(i0 + r) * ldi + j0 + c4 * 4];
    s[r * 33 + c4 * 4 + 0] = f2tf(v.x);
    s[r * 33 + c4 * 4 + 1] = f2tf(v.y);
    s[r * 33 + c4 * 4 + 2] = f2tf(v.z);
    s[r * 33 + c4 * 4 + 3] = f2tf(v.w);
    __syncthreads();
    float4 o;
    o.x = s[(c4 * 4 + 0) * 33 + r];
    o.y = s[(c4 * 4 + 1) * 33 + r];
    o.z = s[(c4 * 4 + 2) * 33 + r];
    o.w = s[(c4 * 4 + 3) * 33 + r];
    *(float4*)&out[(j0 + r) * ldo + i0 + c4 * 4] = o;
}

// ---------- Core A: TF32 MMA, tile 32 x 64, 256 thr, 3-stage cp.async ------
// out[i0..+31][j0..+63] = act(sum_k Wa/Wb[i][k] * X[k][j] (+bias))
// DUALW: W rows come from Wa (k<256) / Wb (k>=256), both stride LDW.
template<int LDW, int LDX, int LDO, bool DUALW, bool ROUND, bool BIASCOL>
__device__ __forceinline__ void gemmA(
    const float* __restrict__ Wa, const float* __restrict__ Wb,
    const float* __restrict__ X, const float* __restrict__ bias,
    float* __restrict__ out, int K, bool relu)
{
    const int n0   = blockIdx.x * 64;
    const int o0   = blockIdx.y * 32;
    const int tid  = threadIdx.x;
    const int warp = tid >> 5, lane = tid & 31;
    const int g    = lane >> 2, t4 = lane & 3;
    const int mt   = warp & 1;
    const int ng   = (warp >> 1) * 16;

    __shared__ __align__(16) float sW[3][32 * 36];
    __shared__ __align__(16) float sX[3][32 * 72];

    const int wo = tid >> 3, wf = tid & 7;
    const int xn4 = tid & 15, xk = tid >> 4;

    const int NIT = K >> 5;

    float4 acc[2] = {make_float4(0.f,0.f,0.f,0.f), make_float4(0.f,0.f,0.f,0.f)};

    auto issue = [&](int tile, int st) {
        const int k0 = tile * 32;
        const float* ws = (!DUALW || k0 < 256)
            ? &Wa[(o0 + wo) * LDW + k0 + wf * 4]
            : &Wb[(o0 + wo) * LDW + (k0 - 256) + wf * 4];
        cp16(s2u(&sW[st][wo * 36 + wf * 4]), ws);
        #pragma unroll
        for (int p = 0; p < 2; p++) {
            const int c = k0 + xk + p * 16;
            cp16(s2u(&sX[st][(xk + p * 16) * 72 + xn4 * 4]),
                 &X[c * LDX + n0 + xn4 * 4]);
        }
    };

    issue(0, 0); CP_COMMIT();
    issue(1, 1); CP_COMMIT();

    for (int it = 0; it < NIT; it++) {
        const int st = it % 3;
        if (it + 2 < NIT) issue(it + 2, (it + 2) % 3);
        CP_COMMIT();
        CP_WAIT2();
        __syncthreads();
        const int ob = mt * 16 + g;
        #pragma unroll
        for (int s = 0; s < 4; s++) {
            const int ks = s * 8;
            float a0 = sW[st][(ob    ) * 36 + ks + t4];
            float a1 = sW[st][(ob + 8) * 36 + ks + t4];
            float a2 = sW[st][(ob    ) * 36 + ks + t4 + 4];
            float a3 = sW[st][(ob + 8) * 36 + ks + t4 + 4];
            #pragma unroll
            for (int j = 0; j < 2; j++) {
                const int nc = ng + j * 8 + g;
                float b0 = sX[st][(ks + t4    ) * 72 + nc];
                float b1 = sX[st][(ks + t4 + 4) * 72 + nc];
                mma_tf32(acc[j], a0, a1, a2, a3, b0, b1);
            }
        }
        __syncthreads();
    }

    const int oA = o0 + mt * 16 + g;
    const int oB = oA + 8;
    #pragma unroll
    for (int j = 0; j < 2; j++) {
        const int nc = n0 + ng + j * 8 + 2 * t4;
        float c0 = acc[j].x, c1 = acc[j].y, c2 = acc[j].z, c3 = acc[j].w;
        if (bias) {
            if (BIASCOL) {
                const float b0 = bias[nc], b1v = bias[nc + 1];
                c0 += b0; c1 += b1v; c2 += b0; c3 += b1v;
            } else {
                const float bA = bias[oA], bB = bias[oB];
                c0 += bA; c1 += bA; c2 += bB; c3 += bB;
            }
        }
        if (relu) {
            c0 = fmaxf(c0, 0.f); c1 = fmaxf(c1, 0.f);
            c2 = fmaxf(c2, 0.f); c3 = fmaxf(c3, 0.f);
        }
        if (ROUND) { c0 = f2tf(c0); c1 = f2tf(c1); c2 = f2tf(c2); c3 = f2tf(c3); }
        *(float2*)&out[oA * LDO + nc] = make_float2(c0, c1);
        *(float2*)&out[oB * LDO + nc] = make_float2(c2, c3);
    }
}

// ---------- Core B: TF32 MMA, tile 16 x 64, 256 thr, 3-stage cp.async ------
// 8 warps each m16 x n8 (r13-proven structure).
template<int LDW, int LDX, int LDO, bool ROUND, bool BIASCOL>
__device__ __forceinline__ void gemmB(
    const float* __restrict__ W, const float* __restrict__ X,
    const float* __restrict__ bias, float* __restrict__ out, int K)
{
    const int n0   = blockIdx.x * 64;
    const int o0   = blockIdx.y * 16;
    const int tid  = threadIdx.x;
    const int warp = tid >> 5, lane = tid & 31;
    const int g    = lane >> 2, t4 = lane & 3;

    __shared__ __align__(16) float sW[3][16 * 36];
    __shared__ __align__(16) float sX[3][32 * 72];

    const int wo = tid >> 3, wf = tid & 7;          // W: tid<128 only
    const int xn4 = tid & 15, xk = tid >> 4;

    const int NIT = K >> 5;

    float4 acc = make_float4(0.f, 0.f, 0.f, 0.f);

    auto issue = [&](int tile, int st) {
        const int k0 = tile * 32;
        if (tid < 128)
            cp16(s2u(&sW[st][wo * 36 + wf * 4]), &W[(o0 + wo) * LDW + k0 + wf * 4]);
        #pragma unroll
        for (int p = 0; p < 2; p++) {
            const int c = k0 + xk + p * 16;
            cp16(s2u(&sX[st][(xk + p * 16) * 72 + xn4 * 4]),
                 &X[c * LDX + n0 + xn4 * 4]);
        }
    };

    issue(0, 0); CP_COMMIT();
    issue(1, 1); CP_COMMIT();

    for (int it = 0; it < NIT; it++) {
        const int st = it % 3;
        if (it + 2 < NIT) issue(it + 2, (it + 2) % 3);
        CP_COMMIT();
        CP_WAIT2();
        __syncthreads();
        const int nc = warp * 8 + g;
        #pragma unroll
        for (int s = 0; s < 4; s++) {
            const int ks = s * 8;
            float a0 = sW[st][(g    ) * 36 + ks + t4];
            float a1 = sW[st][(g + 8) * 36 + ks + t4];
            float a2 = sW[st][(g    ) * 36 + ks + t4 + 4];
            float a3 = sW[st][(g + 8) * 36 + ks + t4 + 4];
            float b0 = sX[st][(ks + t4    ) * 72 + nc];
            float b1 = sX[st][(ks + t4 + 4) * 72 + nc];
            mma_tf32(acc, a0, a1, a2, a3, b0, b1);
        }
        __syncthreads();
    }

    const int oA = o0 + g, oB = oA + 8;
    const int nc = n0 + warp * 8 + 2 * t4;
    float c0 = acc.x, c1 = acc.y, c2 = acc.z, c3 = acc.w;
    if (bias) {
        if (BIASCOL) {
            const float b0 = bias[nc], b1v = bias[nc + 1];
            c0 += b0; c1 += b1v; c2 += b0; c3 += b1v;
        } else {
            const float bA = bias[oA], bB = bias[oB];
            c0 += bA; c1 += bA; c2 += bB; c3 += bB;
        }
    }
    if (ROUND) { c0 = f2tf(c0); c1 = f2tf(c1); c2 = f2tf(c2); c3 = f2tf(c3); }
    *(float2*)&out[oA * LDO + nc] = make_float2(c0, c1);
    *(float2*)&out[oB * LDO + nc] = make_float2(c2, c3);
}

// ---------------- stage kernels ----------------

// aq = w1[:, :D] @ x + b1 ; ak = w1[:, D:] @ src   grid (8,8,2), 256 thr
__global__ void __launch_bounds__(256) k_qk(const float* __restrict__ b1)
{
    if (blockIdx.z == 0)
        gemmA<512, 512, 512, false, false, false>(
            g_w1t, nullptr, g_xt, b1, g_aq, 256, false);
    else
        gemmA<512, 512, 512, false, false, false>(
            g_w1t + 256, nullptr, g_srct, nullptr, g_ak, 256, false);
}

// scores[n][m] = sum_d w2[d]*relu(aq[d][n]+ak[d][m]) + b2   grid (8,16), 256 thr
// (r13-proven SIMT kernel, verbatim)
__global__ void __launch_bounds__(256) k_score(
    const float* __restrict__ w2, const float* __restrict__ b2,
    float* __restrict__ scores)
{
    const int m0  = blockIdx.x * 64;
    const int n0  = blockIdx.y * 32;
    const int tid = threadIdx.x;
    const int wg  = tid >> 7;
    const int t   = tid & 127;
    const int mI  = t & 15;
    const int nG  = t >> 4;

    __shared__ __align__(16) float sA[2][32 * 36];
    __shared__ __align__(16) float sB[2][32 * 68];
    __shared__ float sw[2][32];
    __shared__ __align__(16) float sR[128 * 16];

    const int an4 = t & 7,  adr = t >> 3;
    const int bm4 = t & 15, bdr = t >> 4;
    const int db  = wg * 128;

    float4 ra[2], rb[4];
    float rwv;
    float4 acc[4];
    #pragma unroll
    for (int j = 0; j < 4; j++) acc[j] = make_float4(0.f, 0.f, 0.f, 0.f);

    #pragma unroll
    for (int p = 0; p < 2; p++)
        ra[p] = *(const float4*)&g_aq[(db + adr + p * 16) * 512 + n0 + an4 * 4];
    #pragma unroll
    for (int p = 0; p < 4; p++)
        rb[p] = *(const float4*)&g_ak[(db + bdr + p * 8) * 512 + m0 + bm4 * 4];
    rwv = (t < 32) ? w2[db + t] : 0.f;

    for (int it = 0; it < 4; it++) {
        __syncthreads();
        #pragma unroll
        for (int p = 0; p < 2; p++)
            *(float4*)&sA[wg][(adr + p * 16) * 36 + an4 * 4] = ra[p];
        #pragma unroll
        for (int p = 0; p < 4; p++)
            *(float4*)&sB[wg][(bdr + p * 8) * 68 + bm4 * 4] = rb[p];
        if (t < 32) sw[wg][t] = rwv;
        __syncthreads();

        if (it + 1 < 4) {
            const int d0 = db + (it + 1) * 32;
            #pragma unroll
            for (int p = 0; p < 2; p++)
                ra[p] = *(const float4*)&g_aq[(d0 + adr + p * 16) * 512 + n0 + an4 * 4];
            #pragma unroll
            for (int p = 0; p < 4; p++)
                rb[p] = *(const float4*)&g_ak[(d0 + bdr + p * 8) * 512 + m0 + bm4 * 4];
            if (t < 32) rwv = w2[d0 + t];
        }

        #pragma unroll
        for (int d = 0; d < 32; d++) {
            float4 av = *(const float4*)&sA[wg][d * 36 + nG * 4];
            float4 bv = *(const float4*)&sB[wg][d * 68 + mI * 4];
            float w  = sw[wg][d];
            float a[4] = {av.x, av.y, av.z, av.w};
            #pragma unroll
            for (int j = 0; j < 4; j++) {
                acc[j].x += w * fmaxf(a[j] + bv.x, 0.f);
                acc[j].y += w * fmaxf(a[j] + bv.y, 0.f);
                acc[j].z += w * fmaxf(a[j] + bv.z, 0.f);
                acc[j].w += w * fmaxf(a[j] + bv.w, 0.f);
            }
        }
    }

    if (wg == 1) {
        #pragma unroll
        for (int j = 0; j < 4; j++)
            *(float4*)&sR[(t * 4 + j) * 4] = acc[j];
    }
    __syncthreads();
    if (wg == 0) {
        const float bs = b2[0];
        #pragma unroll
        for (int j = 0; j < 4; j++) {
            float4 r = *(const float4*)&sR[(t * 4 + j) * 4];
            const int n = n0 + nG * 4 + j;
            float4 v = acc[j];
            v.x += r.x + bs; v.y += r.y + bs;
            v.z += r.z + bs; v.w += r.w + bs;
            *(float4*)&scores[n * 512 + m0 + mI * 4] = v;
        }
    }
}

// softmax over m per row n -> prob[n][m] (tf32), COALESCED. 128 x 256 thr,
// 4 rows/block, 2 warps/row, 8 elems/thread. No transpose, no staging.
__global__ void __launch_bounds__(256) k_softmax(const float* __restrict__ scores)
{
    const int n0   = blockIdx.x * 4;
    const int tid  = threadIdx.x;
    const int w    = tid >> 5, lane = tid & 31;
    const int r    = w >> 1, h = w & 1;
    __shared__ float sred[8];

    const int base = (n0 + r) * 512 + h * 256;
    const float* row = scores + base;
    float v[8];
    float mx = -1e30f;
    #pragma unroll
    for (int i = 0; i < 8; i++) { v[i] = row[lane + 32 * i]; mx = fmaxf(mx, v[i]); }
    #pragma unroll
    for (int o = 16; o; o >>= 1) mx = fmaxf(mx, __shfl_xor_sync(0xffffffffu, mx, o));
    if (lane == 0) sred[w] = mx;
    __syncthreads();
    const float m = fmaxf(sred[r * 2], sred[r * 2 + 1]);
    float s = 0.f;
    #pragma unroll
    for (int i = 0; i < 8; i++) { v[i] = __expf(v[i] - m); s += v[i]; }
    #pragma unroll
    for (int o = 16; o; o >>= 1) s += __shfl_xor_sync(0xffffffffu, s, o);
    __syncthreads();
    if (lane == 0) sred[w] = s;
    __syncthreads();
    const float inv = 1.f / (sred[r * 2] + sred[r * 2 + 1]);
    #pragma unroll
    for (int i = 0; i < 8; i++)
        g_prob[base + lane + 32 * i] = f2tf(v[i] * inv);
}

// msgT[n][d] = sum_m prob[n][m] * srcT[m][d]    grid (4,32), 256 thr
__global__ void __launch_bounds__(256) k_msgT()
{
    gemmB<512, 256, 256, true, false>(g_prob, g_srcTt, nullptr, g_msgT, 512);
}

// h2T[n][o] = relu(sum_c catT[n][c]*waT[c][o] + ba[o])   grid (8,16), 256 thr
__global__ void __launch_bounds__(256) k_h2T(const float* __restrict__ ba)
{
    gemmA<256, 512, 512, true, true, true>(
        g_xTt, g_msgT, g_waTt, ba, g_h2T, 512, true);
}

// yT[n][o] = sum_c h2T[n][c]*wbT[c][o] + bb[o]   grid (4,32), 256 thr
__global__ void __launch_bounds__(256) k_yT(const float* __restrict__ bb)
{
    gemmB<512, 256, 256, false, true>(g_h2T, g_wbTt, bb, g_yT, 512);
}

// y[o][n] = yT[n][o]   grid (16,8), 256 thr, 32x32 smem tiles
__global__ void __launch_bounds__(256) k_tr(float* __restrict__ y)
{
    const int nt = blockIdx.x * 32;   // n tile
    const int ot = blockIdx.y * 32;   // o tile
    const int tid = threadIdx.x;
    __shared__ float s[32 * 33];
    const int r = tid >> 3, c4 = tid & 7;
    float4 v = *(const float4*)&g_yT[(nt + r) * 256 + ot + c4 * 4];
    s[r * 33 + c4 * 4 + 0] = v.x;
    s[r * 33 + c4 * 4 + 1] = v.y;
    s[r * 33 + c4 * 4 + 2] = v.z;
    s[r * 33 + c4 * 4 + 3] = v.w;
    __syncthreads();
    float4 o;
    o.x = s[(c4 * 4 + 0) * 33 + r];
    o.y = s[(c4 * 4 + 1) * 33 + r];
    o.z = s[(c4 * 4 + 2) * 33 + r];
    o.w = s[(c4 * 4 + 3) * 33 + r];
    *(float4*)&y[(ot + r) * 512 + nt + c4 * 4] = o;
}

// ---------------- launch ----------------
extern "C" void kernel_launch(void* const* d_in, const int* in_sizes, int n_in,
                              void* d_out, int out_size)
{
    const float* x   = (const float*)d_in[0];
    const float* src = (const float*)d_in[1];
    const float* w1  = (const float*)d_in[2];
    const float* b1  = (const float*)d_in[3];
    const float* w2  = (const float*)d_in[4];
    const float* b2  = (const float*)d_in[5];
    const float* wa  = (const float*)d_in[6];
    const float* ba  = (const float*)d_in[7];
    const float* wb  = (const float*)d_in[8];
    const float* bb  = (const float*)d_in[9];

    float* y      = (float*)d_out;   // (1, D, NQ)
    float* scores = y + D * NQ;      // (1, NQ, NK)

    k_cvt    <<<736,           256>>>(x, src, w1, wa, wb);
    k_qk     <<<dim3(8, 8, 2), 256>>>(b1);
    k_score  <<<dim3(8, 16),   256>>>(w2, b2, scores);
    k_softmax<<<128,           256>>>(scores);
    k_msgT   <<<dim3(4, 32),   256>>>();
    k_h2T    <<<dim3(8, 16),   256>>>(ba);
    k_yT     <<<dim3(4, 32),   256>>>(bb);
    k_tr     <<<dim3(16, 8),   256>>>(y);
}